// round 16
// baseline (speedup 1.0000x reference)
#include <cuda_runtime.h>
#include <cuda_bf16.h>

#define TT 8
#define BB 32
#define CIN 64
#define COUT 128
#define HH 32
#define WW 32
#define NN (TT*BB)          // 256 flattened images
#define HW (HH*WW)          // 1024

__device__ float g_y[(size_t)NN * COUT * HW];   // 134 MB conv output
__device__ float g_scale[COUT];
__device__ float g_shift[COUT];

// ---------------------------------------------------------------------------
// Winograd F(2x2, 3x3) conv (Lavin matrices), fp32 — numerics VERBATIM from
// R7 (measured nearest to the reference conv: sigma^2_conv ~ 0-8 flip units).
//   B^T = [[1,0,-1,0],[0,1,1,0],[0,-1,1,0],[0,1,0,-1]]
//   G   = [[1,0,0],[.5,.5,.5],[.5,-.5,.5],[0,0,1]]
//   A^T = [[1,1,1,0],[0,1,-1,-1]]
// Transform-domain accumulation over ci (fmaf chain ci=0..63).
// Block = (co-group of 4, image n, row-half h). 128 threads = 8x16 tiles of
// 2x2 outputs; per thread 4 co x 16 transform accumulators.
// ---------------------------------------------------------------------------
#define SU_F   (CIN * 16 * 4)        // 4096 floats: U[ci][coef16][co4]
#define SIN_CH 16                    // ci per staged chunk
#define SIN_F  (SIN_CH * 18 * 36)    // 10368 floats
#define SMEM_BYTES ((SU_F + SIN_F) * 4)   // 57856 B

__global__ __launch_bounds__(128) void conv_kernel(
    const float* __restrict__ x,      // [N, CIN, H, W]
    const float* __restrict__ wgt,    // [COUT, CIN, 3, 3]
    const float* __restrict__ bias)   // [COUT]
{
    extern __shared__ float sm[];
    float* su   = sm;                 // filter transforms
    float* sinp = sm + SU_F;          // staged input chunk

    const int cob = blockIdx.x * 4;   // first of 4 output channels
    const int n   = blockIdx.y;
    const int h   = blockIdx.z;       // 0..1: output row half
    const int tid = threadIdx.x;
    const int tr  = tid >> 4;         // local tile row 0..7
    const int tc  = tid & 15;         // tile col 0..15

    // ---- Filter transform U = G g G^T for 4 co x 64 ci ----
    for (int e = tid; e < 4 * CIN; e += 128) {
        const int co = e & 3;
        const int ci = e >> 2;
        const float* gp = wgt + (size_t)(cob + co) * (CIN * 9) + ci * 9;
        float g0[3] = {gp[0], gp[1], gp[2]};
        float g1[3] = {gp[3], gp[4], gp[5]};
        float g2[3] = {gp[6], gp[7], gp[8]};
        float q[4][3];
#pragma unroll
        for (int j = 0; j < 3; j++) {
            q[0][j] = g0[j];
            q[1][j] = __fmul_rn(0.5f, __fadd_rn(__fadd_rn(g0[j], g1[j]), g2[j]));
            q[2][j] = __fmul_rn(0.5f, __fadd_rn(__fsub_rn(g0[j], g1[j]), g2[j]));
            q[3][j] = g2[j];
        }
        float* up = su + ci * 64 + co;      // stride 4 over coef
#pragma unroll
        for (int i = 0; i < 4; i++) {
            float u0 = q[i][0];
            float u1 = __fmul_rn(0.5f, __fadd_rn(__fadd_rn(q[i][0], q[i][1]), q[i][2]));
            float u2 = __fmul_rn(0.5f, __fadd_rn(__fsub_rn(q[i][0], q[i][1]), q[i][2]));
            float u3 = q[i][2];
            up[(i * 4 + 0) * 4] = u0;
            up[(i * 4 + 1) * 4] = u1;
            up[(i * 4 + 2) * 4] = u2;
            up[(i * 4 + 3) * 4] = u3;
        }
    }

    float acc[4][16];
#pragma unroll
    for (int co = 0; co < 4; co++)
#pragma unroll
        for (int k = 0; k < 16; k++) acc[co][k] = 0.f;

    const float* xn = x + (size_t)n * CIN * HW;

    for (int ch = 0; ch < 4; ch++) {
        __syncthreads();
        const int cib = ch * SIN_CH;
        for (int e = tid; e < SIN_CH * 18 * 34; e += 128) {
            const int cl  = e / 612;          // 18*34
            const int rem = e - cl * 612;
            const int r   = rem / 34;
            const int c   = rem - r * 34;
            const int grow = h * 16 + r - 1;
            const int gcol = c - 1;
            float v = 0.f;
            if ((unsigned)grow < 32u && (unsigned)gcol < 32u)
                v = xn[(cib + cl) * HW + grow * 32 + gcol];
            sinp[cl * 648 + r * 36 + c] = v;   // 648 = 18*36
        }
        __syncthreads();

        for (int cl = 0; cl < SIN_CH; cl++) {
            const float* p = sinp + cl * 648 + (2 * tr) * 36 + 2 * tc;
            float d0[4], d1[4], d2[4], d3[4];
#pragma unroll
            for (int j = 0; j < 4; j++) d0[j] = p[j];
#pragma unroll
            for (int j = 0; j < 4; j++) d1[j] = p[36 + j];
#pragma unroll
            for (int j = 0; j < 4; j++) d2[j] = p[72 + j];
#pragma unroll
            for (int j = 0; j < 4; j++) d3[j] = p[108 + j];

            float t0[4], t1[4], t2[4], t3[4];
#pragma unroll
            for (int j = 0; j < 4; j++) {
                t0[j] = __fsub_rn(d0[j], d2[j]);
                t1[j] = __fadd_rn(d1[j], d2[j]);
                t2[j] = __fsub_rn(d2[j], d1[j]);
                t3[j] = __fsub_rn(d1[j], d3[j]);
            }
            float V[16];
#pragma unroll
            for (int i = 0; i < 4; i++) {
                const float* ti = (i == 0) ? t0 : (i == 1) ? t1 : (i == 2) ? t2 : t3;
                V[i * 4 + 0] = __fsub_rn(ti[0], ti[2]);
                V[i * 4 + 1] = __fadd_rn(ti[1], ti[2]);
                V[i * 4 + 2] = __fsub_rn(ti[2], ti[1]);
                V[i * 4 + 3] = __fsub_rn(ti[1], ti[3]);
            }

            const float* up = su + (cib + cl) * 64;
#pragma unroll
            for (int k = 0; k < 16; k++) {
                const float vk = V[k];
                const float4 u4 = *reinterpret_cast<const float4*>(up + k * 4);
                acc[0][k] = fmaf(u4.x, vk, acc[0][k]);
                acc[1][k] = fmaf(u4.y, vk, acc[1][k]);
                acc[2][k] = fmaf(u4.z, vk, acc[2][k]);
                acc[3][k] = fmaf(u4.w, vk, acc[3][k]);
            }
        }
    }

    // ---- Inverse transform A^T m A + bias, store y ----
    const int gtr   = h * 8 + tr;
    const int grow0 = 2 * gtr;
    const int gcol0 = 2 * tc;
#pragma unroll
    for (int co = 0; co < 4; co++) {
        const float* m = acc[co];
        float p0[4], p1[4];
#pragma unroll
        for (int j = 0; j < 4; j++) {
            p0[j] = __fadd_rn(__fadd_rn(m[0 + j], m[4 + j]), m[8 + j]);
            p1[j] = __fsub_rn(__fsub_rn(m[4 + j], m[8 + j]), m[12 + j]);
        }
        const float bv = __ldg(&bias[cob + co]);
        float o00 = __fadd_rn(__fadd_rn(__fadd_rn(p0[0], p0[1]), p0[2]), bv);
        float o01 = __fadd_rn(__fsub_rn(__fsub_rn(p0[1], p0[2]), p0[3]), bv);
        float o10 = __fadd_rn(__fadd_rn(__fadd_rn(p1[0], p1[1]), p1[2]), bv);
        float o11 = __fadd_rn(__fsub_rn(__fsub_rn(p1[1], p1[2]), p1[3]), bv);

        float* yb = g_y + ((size_t)n * COUT + cob + co) * HW + grow0 * 32 + gcol0;
        *reinterpret_cast<float2*>(yb)      = make_float2(o00, o01);
        *reinterpret_cast<float2*>(yb + 32) = make_float2(o10, o11);
    }
}

// ---------------------------------------------------------------------------
// BN stats: persistent 8-accumulator vectorized fp32 reduction (NEON VF4 x
// IC2) — VERBATIM from R14 (measured: residual sigma^2 <= 8 flip units).
// Lane j (0..7) sums elements i == j (mod 8) over (n, hw) row-major.
// Combine: lanewise acc0+acc1 (A_j + A_{j+4}), then faddp pair tree.
// ---------------------------------------------------------------------------
__global__ __launch_bounds__(32) void vecstats_kernel(
    const float* __restrict__ gamma, const float* __restrict__ beta)
{
    const int c    = blockIdx.x;      // 0..127
    const int lane = threadIdx.x;     // 0..31 (0..7 active)

    const float* base = g_y + (size_t)c * HW;

    float a = 0.f;
    if (lane < 8) {
        for (int n = 0; n < NN; n++) {
            const float* p = base + (size_t)n * COUT * HW + lane;
            for (int i = 0; i < HW / 8; i++)
                a = __fadd_rn(a, p[i * 8]);
        }
    }
    float A0 = __shfl_sync(0xFFFFFFFFu, a, 0), A1 = __shfl_sync(0xFFFFFFFFu, a, 1);
    float A2 = __shfl_sync(0xFFFFFFFFu, a, 2), A3 = __shfl_sync(0xFFFFFFFFu, a, 3);
    float A4 = __shfl_sync(0xFFFFFFFFu, a, 4), A5 = __shfl_sync(0xFFFFFFFFu, a, 5);
    float A6 = __shfl_sync(0xFFFFFFFFu, a, 6), A7 = __shfl_sync(0xFFFFFFFFu, a, 7);
    float l0 = __fadd_rn(A0, A4), l1 = __fadd_rn(A1, A5);
    float l2 = __fadd_rn(A2, A6), l3 = __fadd_rn(A3, A7);
    float total = __fadd_rn(__fadd_rn(l0, l1), __fadd_rn(l2, l3));
    const float mean = __fdiv_rn(total, 262144.0f);   // 2^18, exact

    float q = 0.f;
    if (lane < 8) {
        for (int n = 0; n < NN; n++) {
            const float* p = base + (size_t)n * COUT * HW + lane;
            for (int i = 0; i < HW / 8; i++) {
                float d = __fsub_rn(p[i * 8], mean);
                q = __fadd_rn(q, __fmul_rn(d, d));
            }
        }
    }
    A0 = __shfl_sync(0xFFFFFFFFu, q, 0); A1 = __shfl_sync(0xFFFFFFFFu, q, 1);
    A2 = __shfl_sync(0xFFFFFFFFu, q, 2); A3 = __shfl_sync(0xFFFFFFFFu, q, 3);
    A4 = __shfl_sync(0xFFFFFFFFu, q, 4); A5 = __shfl_sync(0xFFFFFFFFu, q, 5);
    A6 = __shfl_sync(0xFFFFFFFFu, q, 6); A7 = __shfl_sync(0xFFFFFFFFu, q, 7);
    l0 = __fadd_rn(A0, A4); l1 = __fadd_rn(A1, A5);
    l2 = __fadd_rn(A2, A6); l3 = __fadd_rn(A3, A7);
    float total2 = __fadd_rn(__fadd_rn(l0, l1), __fadd_rn(l2, l3));
    const float var = __fdiv_rn(total2, 262144.0f);

    if (lane == 0) {
        float rs    = __fdiv_rn(1.0f, __fsqrt_rn(__fadd_rn(var, 1e-5f)));
        float inv   = __fmul_rn(gamma[c], rs);
        float shift = __fsub_rn(beta[c], __fmul_rn(mean, inv));
        g_scale[c] = inv;
        g_shift[c] = shift;
    }
}

// LIF recurrence — strict fp32, no FMA contraction (unchanged).
__global__ __launch_bounds__(256) void lif_kernel(float* __restrict__ out) {
    const int gid = blockIdx.x * 256 + threadIdx.x;
    if (gid >= BB * COUT * HW) return;
    const int c = (gid >> 10) & (COUT - 1);
    const float sc = g_scale[c];
    const float sh = g_shift[c];

    float mem = 0.f;
    size_t idx = (size_t)gid;
#pragma unroll
    for (int t = 0; t < TT; t++) {
        float v = __fadd_rn(__fmul_rn(g_y[idx], sc), sh);
        mem = __fadd_rn(__fmul_rn(mem, 0.99f), v);
        float u = __fsub_rn(mem, 1.0f);
        float spike = (u > 0.0f) ? 1.0f : 0.0f;
        out[idx] = spike;
        mem = __fsub_rn(mem, __fmul_rn(spike, 1.0f));
        idx += (size_t)BB * COUT * HW;
    }
}

extern "C" void kernel_launch(void* const* d_in, const int* in_sizes, int n_in,
                              void* d_out, int out_size) {
    const float* x      = (const float*)d_in[0];
    const float* conv_w = (const float*)d_in[1];
    const float* conv_b = (const float*)d_in[2];
    const float* gamma  = (const float*)d_in[3];
    const float* beta   = (const float*)d_in[4];
    float* out = (float*)d_out;

    cudaFuncSetAttribute(conv_kernel,
                         cudaFuncAttributeMaxDynamicSharedMemorySize, SMEM_BYTES);

    dim3 grid(COUT / 4, NN, 2);
    conv_kernel<<<grid, 128, SMEM_BYTES>>>(x, conv_w, conv_b);
    vecstats_kernel<<<COUT, 32>>>(gamma, beta);
    lif_kernel<<<(BB * COUT * HW + 255) / 256, 256>>>(out);
}

// round 17
// speedup vs baseline: 1.2577x; 1.2577x over previous
#include <cuda_runtime.h>
#include <cuda_bf16.h>

#define TT 8
#define BB 32
#define CIN 64
#define COUT 128
#define HH 32
#define WW 32
#define NN (TT*BB)          // 256 flattened images
#define HW (HH*WW)          // 1024

__device__ float g_y[(size_t)NN * COUT * HW];            // 134 MB conv output
__device__ float g_V[(size_t)NN * 2 * CIN * 16 * 128];   // 268 MB input transforms
__device__ float g_U[(size_t)32 * CIN * 16 * 4];         // 512 KB filter transforms
__device__ float g_scale[COUT];
__device__ float g_shift[COUT];

// ---------------------------------------------------------------------------
// Stage 1: filter transform U = G g G^T. Ops BIT-IDENTICAL to the passing
// R16 kernel's per-block filter transform (same __fmul_rn/__fadd_rn order).
// One thread per (co, ci). Layout matches the old su smem layout per co-group:
// g_U[g(32)][ci(64)][coef(16)][co4] with g = co/4.
// ---------------------------------------------------------------------------
__global__ __launch_bounds__(256) void wtrans_kernel(
    const float* __restrict__ wgt)    // [COUT, CIN, 3, 3]
{
    const int gid = blockIdx.x * 256 + threadIdx.x;   // 0..8191
    const int g  = gid >> 8;          // co-group 0..31
    const int e  = gid & 255;
    const int co = e & 3;
    const int ci = e >> 2;
    const float* gp = wgt + (size_t)(g * 4 + co) * (CIN * 9) + ci * 9;
    float g0[3] = {gp[0], gp[1], gp[2]};
    float g1[3] = {gp[3], gp[4], gp[5]};
    float g2[3] = {gp[6], gp[7], gp[8]};
    float q[4][3];
#pragma unroll
    for (int j = 0; j < 3; j++) {
        q[0][j] = g0[j];
        q[1][j] = __fmul_rn(0.5f, __fadd_rn(__fadd_rn(g0[j], g1[j]), g2[j]));
        q[2][j] = __fmul_rn(0.5f, __fadd_rn(__fsub_rn(g0[j], g1[j]), g2[j]));
        q[3][j] = g2[j];
    }
    float* up = g_U + (size_t)g * 4096 + ci * 64 + co;
#pragma unroll
    for (int i = 0; i < 4; i++) {
        float u0 = q[i][0];
        float u1 = __fmul_rn(0.5f, __fadd_rn(__fadd_rn(q[i][0], q[i][1]), q[i][2]));
        float u2 = __fmul_rn(0.5f, __fadd_rn(__fsub_rn(q[i][0], q[i][1]), q[i][2]));
        float u3 = q[i][2];
        up[(i * 4 + 0) * 4] = u0;
        up[(i * 4 + 1) * 4] = u1;
        up[(i * 4 + 2) * 4] = u2;
        up[(i * 4 + 3) * 4] = u3;
    }
}

// ---------------------------------------------------------------------------
// Stage 2: input transform V = B^T d B, computed ONCE per (n,h,ci,tile)
// (was recomputed in 32 co-blocks). Staging + transform ops BIT-IDENTICAL to
// R16. Layout g_V[n][h][ci][k(16)][tile(128)] -> coalesced writes per k and
// coalesced k-strided reads in stage 3.
// ---------------------------------------------------------------------------
#define ACH 8
__global__ __launch_bounds__(128) void itrans_kernel(
    const float* __restrict__ x)      // [N, CIN, H, W]
{
    __shared__ float sinp[ACH * 18 * 36];   // 648 per plane

    const int h   = blockIdx.x;       // 0..1
    const int n   = blockIdx.y;
    const int tid = threadIdx.x;      // tile id 0..127
    const int tr  = tid >> 4;
    const int tc  = tid & 15;

    const float* xn = x + (size_t)n * CIN * HW;
    float* vb = g_V + ((size_t)(n * 2 + h) * CIN) * 2048 + tid;  // + ci*2048 + k*128

    for (int ch = 0; ch < CIN / ACH; ch++) {
        __syncthreads();
        const int cib = ch * ACH;
        for (int e = tid; e < ACH * 18 * 34; e += 128) {
            const int cl  = e / 612;
            const int rem = e - cl * 612;
            const int r   = rem / 34;
            const int c   = rem - r * 34;
            const int grow = h * 16 + r - 1;
            const int gcol = c - 1;
            float v = 0.f;
            if ((unsigned)grow < 32u && (unsigned)gcol < 32u)
                v = xn[(cib + cl) * HW + grow * 32 + gcol];
            sinp[cl * 648 + r * 36 + c] = v;
        }
        __syncthreads();

        for (int cl = 0; cl < ACH; cl++) {
            const float* p = sinp + cl * 648 + (2 * tr) * 36 + 2 * tc;
            float d0[4], d1[4], d2[4], d3[4];
#pragma unroll
            for (int j = 0; j < 4; j++) d0[j] = p[j];
#pragma unroll
            for (int j = 0; j < 4; j++) d1[j] = p[36 + j];
#pragma unroll
            for (int j = 0; j < 4; j++) d2[j] = p[72 + j];
#pragma unroll
            for (int j = 0; j < 4; j++) d3[j] = p[108 + j];

            float t0[4], t1[4], t2[4], t3[4];
#pragma unroll
            for (int j = 0; j < 4; j++) {
                t0[j] = __fsub_rn(d0[j], d2[j]);
                t1[j] = __fadd_rn(d1[j], d2[j]);
                t2[j] = __fsub_rn(d2[j], d1[j]);
                t3[j] = __fsub_rn(d1[j], d3[j]);
            }
            float V[16];
#pragma unroll
            for (int i = 0; i < 4; i++) {
                const float* ti = (i == 0) ? t0 : (i == 1) ? t1 : (i == 2) ? t2 : t3;
                V[i * 4 + 0] = __fsub_rn(ti[0], ti[2]);
                V[i * 4 + 1] = __fadd_rn(ti[1], ti[2]);
                V[i * 4 + 2] = __fsub_rn(ti[2], ti[1]);
                V[i * 4 + 3] = __fsub_rn(ti[1], ti[3]);
            }
            float* vp = vb + (size_t)(cib + cl) * 2048;
#pragma unroll
            for (int k = 0; k < 16; k++) vp[k * 128] = V[k];
        }
    }
}

// ---------------------------------------------------------------------------
// Stage 3: transform-domain GEMM + inverse transform + bias + store y.
// Same fmaf accumulation chain over ci = 0..63 (ascending), same inverse
// transform / bias ops as R16 -> outputs bit-identical. No input staging,
// no main-loop barriers; smem = 16KB U only -> higher occupancy.
// ---------------------------------------------------------------------------
__global__ __launch_bounds__(128) void wgemm_kernel(
    const float* __restrict__ bias)   // [COUT]
{
    __shared__ float su[4096];        // U for this co-group: [ci][coef16][co4]

    const int g   = blockIdx.x;       // co-group 0..31
    const int cob = g * 4;
    const int n   = blockIdx.y;
    const int h   = blockIdx.z;
    const int tid = threadIdx.x;      // tile 0..127
    const int tr  = tid >> 4;
    const int tc  = tid & 15;

    // Load U (16 KB, coalesced).
    const float* gu = g_U + (size_t)g * 4096;
    for (int i = tid; i < 4096; i += 128) su[i] = gu[i];
    __syncthreads();

    float acc[4][16];
#pragma unroll
    for (int co = 0; co < 4; co++)
#pragma unroll
        for (int k = 0; k < 16; k++) acc[co][k] = 0.f;

    const float* vbase = g_V + ((size_t)(n * 2 + h) * CIN) * 2048 + tid;

#pragma unroll 2
    for (int ci = 0; ci < CIN; ci++) {
        const float* vp = vbase + (size_t)ci * 2048;
        float V[16];
#pragma unroll
        for (int k = 0; k < 16; k++) V[k] = __ldg(vp + k * 128);
        const float* up = su + ci * 64;
#pragma unroll
        for (int k = 0; k < 16; k++) {
            const float vk = V[k];
            const float4 u4 = *reinterpret_cast<const float4*>(up + k * 4);
            acc[0][k] = fmaf(u4.x, vk, acc[0][k]);
            acc[1][k] = fmaf(u4.y, vk, acc[1][k]);
            acc[2][k] = fmaf(u4.z, vk, acc[2][k]);
            acc[3][k] = fmaf(u4.w, vk, acc[3][k]);
        }
    }

    // Inverse transform A^T m A + bias, store (ops identical to R16).
    const int gtr   = h * 8 + tr;
    const int grow0 = 2 * gtr;
    const int gcol0 = 2 * tc;
#pragma unroll
    for (int co = 0; co < 4; co++) {
        const float* m = acc[co];
        float p0[4], p1[4];
#pragma unroll
        for (int j = 0; j < 4; j++) {
            p0[j] = __fadd_rn(__fadd_rn(m[0 + j], m[4 + j]), m[8 + j]);
            p1[j] = __fsub_rn(__fsub_rn(m[4 + j], m[8 + j]), m[12 + j]);
        }
        const float bv = __ldg(&bias[cob + co]);
        float o00 = __fadd_rn(__fadd_rn(__fadd_rn(p0[0], p0[1]), p0[2]), bv);
        float o01 = __fadd_rn(__fsub_rn(__fsub_rn(p0[1], p0[2]), p0[3]), bv);
        float o10 = __fadd_rn(__fadd_rn(__fadd_rn(p1[0], p1[1]), p1[2]), bv);
        float o11 = __fadd_rn(__fsub_rn(__fsub_rn(p1[1], p1[2]), p1[3]), bv);

        float* yb = g_y + ((size_t)n * COUT + cob + co) * HW + grow0 * 32 + gcol0;
        *reinterpret_cast<float2*>(yb)      = make_float2(o00, o01);
        *reinterpret_cast<float2*>(yb + 32) = make_float2(o10, o11);
    }
}

// ---------------------------------------------------------------------------
// BN stats: persistent 8-accumulator vectorized fp32 reduction — VERBATIM
// (numerics frozen: this exact structure passed).
// ---------------------------------------------------------------------------
__global__ __launch_bounds__(32) void vecstats_kernel(
    const float* __restrict__ gamma, const float* __restrict__ beta)
{
    const int c    = blockIdx.x;
    const int lane = threadIdx.x;

    const float* base = g_y + (size_t)c * HW;

    float a = 0.f;
    if (lane < 8) {
        for (int n = 0; n < NN; n++) {
            const float* p = base + (size_t)n * COUT * HW + lane;
            for (int i = 0; i < HW / 8; i++)
                a = __fadd_rn(a, p[i * 8]);
        }
    }
    float A0 = __shfl_sync(0xFFFFFFFFu, a, 0), A1 = __shfl_sync(0xFFFFFFFFu, a, 1);
    float A2 = __shfl_sync(0xFFFFFFFFu, a, 2), A3 = __shfl_sync(0xFFFFFFFFu, a, 3);
    float A4 = __shfl_sync(0xFFFFFFFFu, a, 4), A5 = __shfl_sync(0xFFFFFFFFu, a, 5);
    float A6 = __shfl_sync(0xFFFFFFFFu, a, 6), A7 = __shfl_sync(0xFFFFFFFFu, a, 7);
    float l0 = __fadd_rn(A0, A4), l1 = __fadd_rn(A1, A5);
    float l2 = __fadd_rn(A2, A6), l3 = __fadd_rn(A3, A7);
    float total = __fadd_rn(__fadd_rn(l0, l1), __fadd_rn(l2, l3));
    const float mean = __fdiv_rn(total, 262144.0f);

    float q = 0.f;
    if (lane < 8) {
        for (int n = 0; n < NN; n++) {
            const float* p = base + (size_t)n * COUT * HW + lane;
            for (int i = 0; i < HW / 8; i++) {
                float d = __fsub_rn(p[i * 8], mean);
                q = __fadd_rn(q, __fmul_rn(d, d));
            }
        }
    }
    A0 = __shfl_sync(0xFFFFFFFFu, q, 0); A1 = __shfl_sync(0xFFFFFFFFu, q, 1);
    A2 = __shfl_sync(0xFFFFFFFFu, q, 2); A3 = __shfl_sync(0xFFFFFFFFu, q, 3);
    A4 = __shfl_sync(0xFFFFFFFFu, q, 4); A5 = __shfl_sync(0xFFFFFFFFu, q, 5);
    A6 = __shfl_sync(0xFFFFFFFFu, q, 6); A7 = __shfl_sync(0xFFFFFFFFu, q, 7);
    l0 = __fadd_rn(A0, A4); l1 = __fadd_rn(A1, A5);
    l2 = __fadd_rn(A2, A6); l3 = __fadd_rn(A3, A7);
    float total2 = __fadd_rn(__fadd_rn(l0, l1), __fadd_rn(l2, l3));
    const float var = __fdiv_rn(total2, 262144.0f);

    if (lane == 0) {
        float rs    = __fdiv_rn(1.0f, __fsqrt_rn(__fadd_rn(var, 1e-5f)));
        float inv   = __fmul_rn(gamma[c], rs);
        float shift = __fsub_rn(beta[c], __fmul_rn(mean, inv));
        g_scale[c] = inv;
        g_shift[c] = shift;
    }
}

// LIF recurrence — strict fp32, no FMA contraction (VERBATIM).
__global__ __launch_bounds__(256) void lif_kernel(float* __restrict__ out) {
    const int gid = blockIdx.x * 256 + threadIdx.x;
    if (gid >= BB * COUT * HW) return;
    const int c = (gid >> 10) & (COUT - 1);
    const float sc = g_scale[c];
    const float sh = g_shift[c];

    float mem = 0.f;
    size_t idx = (size_t)gid;
#pragma unroll
    for (int t = 0; t < TT; t++) {
        float v = __fadd_rn(__fmul_rn(g_y[idx], sc), sh);
        mem = __fadd_rn(__fmul_rn(mem, 0.99f), v);
        float u = __fsub_rn(mem, 1.0f);
        float spike = (u > 0.0f) ? 1.0f : 0.0f;
        out[idx] = spike;
        mem = __fsub_rn(mem, __fmul_rn(spike, 1.0f));
        idx += (size_t)BB * COUT * HW;
    }
}

extern "C" void kernel_launch(void* const* d_in, const int* in_sizes, int n_in,
                              void* d_out, int out_size) {
    const float* x      = (const float*)d_in[0];
    const float* conv_w = (const float*)d_in[1];
    const float* conv_b = (const float*)d_in[2];
    const float* gamma  = (const float*)d_in[3];
    const float* beta   = (const float*)d_in[4];
    float* out = (float*)d_out;

    wtrans_kernel<<<32, 256>>>(conv_w);
    dim3 gA(2, NN);
    itrans_kernel<<<gA, 128>>>(x);
    dim3 gB(32, NN, 2);
    wgemm_kernel<<<gB, 128>>>(conv_b);
    vecstats_kernel<<<COUT, 32>>>(gamma, beta);
    lif_kernel<<<(BB * COUT * HW + 255) / 256, 256>>>(out);
}